// round 5
// baseline (speedup 1.0000x reference)
#include <cuda_runtime.h>

#define NB    512
#define NKV   512
#define DIM   256
#define NH    8
#define DH    64
#define INNER 512
#define TOPK  4

#define OUT_ELEMS   (NB * DIM)          // 131072
#define IDX_BASE    OUT_ELEMS
#define IDX_ELEMS   (NB * TOPK)

typedef unsigned long long ull;

// ---------------- device scratch ----------------
__device__ float g_Q   [NB * INNER];        // [b][h*64+e]
__device__ float g_T   [NB * 2048];         // [b][c*8+h]
__device__ float g_W2  [2048 * DIM];        // [(h*256+d)][o]
__device__ float g_CTXF[NB * 2048];         // [b][h*256+d]
__device__ float g_P   [8 * NB * DIM];      // split-K partials

// ---------------- f32x2 helpers ----------------
__device__ __forceinline__ void ffma2(ull& d, ull a, ull b) {
    asm("fma.rn.f32x2 %0, %1, %2, %0;" : "+l"(d) : "l"(a), "l"(b));
}
__device__ __forceinline__ ull dup2(float x) {
    ull r; asm("mov.b64 %0, {%1, %1};" : "=l"(r) : "f"(x)); return r;
}
__device__ __forceinline__ void unpack2(ull v, float& lo, float& hi) {
    asm("mov.b64 {%0, %1}, %2;" : "=f"(lo), "=f"(hi) : "l"(v));
}

// ========== unified small GEMM: 64x64 tile, K in 64-chunks, f32x2 micro ==========
// mode 0: g_Q = inp_q(pA)[512x256] @ Wq(pB)[256x512]            grid(8,8,1)
// mode 1: g_T[b][c*8+h] = sum_e g_Q[b,h,e]*Wk(pB)[c,h,e]        grid(4,8,8) z=h
// mode 2: g_W2[(h*256+d)][o] = sum_e Wv(pA)[d,h,e]*Wo(pB)[h,e,o] grid(4,4,8) z=h
// mode 3: g_P[z] = g_CTXF[:, z*256:(z+1)*256] @ g_W2[z*256:...]  grid(4,8,8) z=ksplit
__global__ __launch_bounds__(256) void k_mm64(const float* __restrict__ pA,
                                              const float* __restrict__ pB,
                                              int mode) {
    __shared__ float As[64 * 68];   // [k][m]
    __shared__ float Bs[64 * 68];   // [k][n]
    const int tid = threadIdx.x;
    const int tr = tid >> 4, tc = tid & 15;
    const int n0 = blockIdx.x * 64, m0 = blockIdx.y * 64;
    const int z = blockIdx.z;

    const float* A; const float* B; float* C;
    int lda, ldb, ldc, chunks; bool bkc = false, scat = false;
    if (mode == 0) { A = pA;              lda = 256;  B = pB;                  ldb = 512; C = g_Q;                 ldc = 512;  chunks = 4; }
    else if (mode == 1) { A = g_Q + z * 64; lda = 512; B = pB + z * 64;        ldb = 512; C = g_T;                 ldc = 2048; chunks = 1; bkc = true; scat = true; }
    else if (mode == 2) { A = pA + z * 64; lda = 512;  B = pB + z * 64 * 256;  ldb = 256; C = g_W2 + z * 65536;    ldc = 256;  chunks = 1; }
    else { A = g_CTXF + z * 256; lda = 2048; B = g_W2 + z * 256 * 256;         ldb = 256; C = g_P + (size_t)z * (NB * DIM); ldc = 256; chunks = 4; }

    ull acc[2][4];
    #pragma unroll
    for (int p = 0; p < 2; p++)
        #pragma unroll
        for (int j = 0; j < 4; j++) acc[p][j] = 0ull;

    for (int ch = 0; ch < chunks; ch++) {
        const int kb = ch * 64;
        #pragma unroll
        for (int s = 0; s < 16; s++) {
            int id = tid + 256 * s;
            int k = id & 63, m = id >> 6;
            As[k * 68 + m] = A[(size_t)(m0 + m) * lda + kb + k];
        }
        if (bkc) {
            #pragma unroll
            for (int s = 0; s < 16; s++) {
                int id = tid + 256 * s;
                int k = id & 63, n = id >> 6;
                Bs[k * 68 + n] = B[(size_t)(n0 + n) * ldb + kb + k];
            }
        } else {
            #pragma unroll
            for (int s = 0; s < 16; s++) {
                int id = tid + 256 * s;
                int n = id & 63, k = id >> 6;
                Bs[k * 68 + n] = B[(size_t)(kb + k) * ldb + n0 + n];
            }
        }
        __syncthreads();
        #pragma unroll 8
        for (int e = 0; e < 64; e++) {
            ulonglong2 a2 = *(const ulonglong2*)&As[e * 68 + tr * 4];
            float4 b4 = *(const float4*)&Bs[e * 68 + tc * 4];
            ull d0 = dup2(b4.x), d1 = dup2(b4.y), d2 = dup2(b4.z), d3 = dup2(b4.w);
            ffma2(acc[0][0], a2.x, d0); ffma2(acc[0][1], a2.x, d1);
            ffma2(acc[0][2], a2.x, d2); ffma2(acc[0][3], a2.x, d3);
            ffma2(acc[1][0], a2.y, d0); ffma2(acc[1][1], a2.y, d1);
            ffma2(acc[1][2], a2.y, d2); ffma2(acc[1][3], a2.y, d3);
        }
        __syncthreads();
    }

    #pragma unroll
    for (int p = 0; p < 2; p++) {
        #pragma unroll
        for (int j = 0; j < 4; j++) {
            float lo, hi; unpack2(acc[p][j], lo, hi);
            int m = m0 + tr * 4 + 2 * p;
            int n = n0 + tc * 4 + j;
            if (scat) {
                g_T[(size_t)m * 2048 + n * 8 + z]       = lo;
                g_T[(size_t)(m + 1) * 2048 + n * 8 + z] = hi;
            } else {
                C[(size_t)m * ldc + n]       = lo;
                C[(size_t)(m + 1) * ldc + n] = hi;
            }
        }
    }
}

// ========== attention: 16 x 32-row kv tiles, double-buffered ==========
#define A_KV0 0          // 32*260 = 8320
#define A_KV1 8320       // 8320
#define A_T   16640      // 2048  [c][h]
#define A_E   18688      // 4096  [j 0..511][h]
#define A_PF  22784      // 2048  [cg][j][h]
#define A_NEG 24832      // 512
#define A_HS  25344      // 512
#define A_RDN 25856      // 8
#define A_WV  25864      // 8
#define A_WI  25872      // 8
#define A_FLOATS 25880
#define AT_BYTES (A_FLOATS * 4)

__global__ __launch_bounds__(256, 2) void k_attn(
        const float* __restrict__ kv_all, const int* __restrict__ mask_all,
        float* __restrict__ outp, int out_size) {
    extern __shared__ float sm[];
    float* s_t   = sm + A_T;
    float* s_e   = sm + A_E;
    float* s_pf  = sm + A_PF;
    float* s_neg = sm + A_NEG;
    float* s_hs  = sm + A_HS;
    float* s_rdn = sm + A_RDN;
    float* s_wv  = sm + A_WV;
    int*   s_wi  = (int*)(sm + A_WI);

    const int b   = blockIdx.x;
    const int tid = threadIdx.x;
    const int wrp = tid >> 5, lane = tid & 31;
    const int rp  = lane, cg = wrp;              // pass1: row rp, c-range [cg*32, cg*32+32)
    const int qd  = tid & 63, rq = tid >> 6;     // ctx: cols 4qd..4qd+3, rows [rq*8, rq*8+8)

    const float4* kvg = (const float4*)(kv_all + (size_t)b * NKV * DIM);

    // T[b] -> s_t ; mask -> s_neg
    {
        const float4* T4 = (const float4*)(g_T + (size_t)b * 2048);
        ((float4*)s_t)[tid]       = T4[tid];
        ((float4*)s_t)[tid + 256] = T4[tid + 256];
        const int* mb = mask_all + b * NKV;
        s_neg[tid]       = mb[tid]       ? 0.0f : -10000.0f;
        s_neg[tid + 256] = mb[tid + 256] ? 0.0f : -10000.0f;
    }

    // preload tile 0 into buffer 0
    float4 pf[8];
    #pragma unroll
    for (int s = 0; s < 8; s++) {
        int id = tid + 256 * s;
        pf[s] = kvg[(id >> 6) * 64 + (id & 63)];
    }
    #pragma unroll
    for (int s = 0; s < 8; s++) {
        int id = tid + 256 * s;
        *(float4*)&sm[A_KV0 + (id >> 6) * 260 + (id & 63) * 4] = pf[s];
    }
    __syncthreads();

    ull ctxa[4][4];
    #pragma unroll
    for (int i = 0; i < 4; i++)
        #pragma unroll
        for (int j = 0; j < 4; j++) ctxa[i][j] = 0ull;

    for (int t = 0; t < 16; t++) {
        float* cur = sm + A_KV0 + (t & 1) * 8320;
        float* nxt = sm + A_KV0 + ((t + 1) & 1) * 8320;

        // issue global loads for next tile (latency hidden by pass1)
        if (t < 15) {
            #pragma unroll
            for (int s = 0; s < 8; s++) {
                int id = tid + 256 * s;
                pf[s] = kvg[((t + 1) * 32 + (id >> 6)) * 64 + (id & 63)];
            }
        }

        // ---- pass1: dots partials (row rp, 32 c of group cg, all 8 heads)
        ull acc[4] = {0ull, 0ull, 0ull, 0ull};
        const int c0 = cg * 32;
        #pragma unroll
        for (int c4 = 0; c4 < 32; c4 += 4) {
            float4 ka = *(const float4*)&cur[rp * 260 + c0 + c4];
            float kf[4] = {ka.x, ka.y, ka.z, ka.w};
            #pragma unroll
            for (int cc = 0; cc < 4; cc++) {
                const float* tp = &s_t[(c0 + c4 + cc) * 8];
                ulonglong2 t01 = *(const ulonglong2*)tp;
                ulonglong2 t23 = *(const ulonglong2*)(tp + 4);
                ull da = dup2(kf[cc]);
                ffma2(acc[0], da, t01.x); ffma2(acc[1], da, t01.y);
                ffma2(acc[2], da, t23.x); ffma2(acc[3], da, t23.y);
            }
        }
        {   // s_pf float layout [cg][j][h] : ull idx cg*128 + rp*4 + hp
            ulonglong2* sp2 = (ulonglong2*)s_pf;
            int base = cg * 64 + rp * 2;
            sp2[base]     = make_ulonglong2(acc[0], acc[1]);
            sp2[base + 1] = make_ulonglong2(acc[2], acc[3]);
        }
        __syncthreads();

        // ---- reduce 8 c-groups + exp (1 value per thread)
        {
            int j = tid >> 3, h = tid & 7;
            float sum = 0.0f;
            #pragma unroll
            for (int g = 0; g < 8; g++) sum += s_pf[g * 256 + j * 8 + h];
            s_e[(t * 32 + j) * 8 + h] = __expf(sum * 0.125f + s_neg[t * 32 + j]);
        }

        // store next tile into the idle buffer
        if (t < 15) {
            #pragma unroll
            for (int s = 0; s < 8; s++) {
                int id = tid + 256 * s;
                *(float4*)&nxt[(id >> 6) * 260 + (id & 63) * 4] = pf[s];
            }
        }
        __syncthreads();

        // ---- ctx accumulate from cur (8 rows per thread)
        #pragma unroll
        for (int jj = 0; jj < 8; jj++) {
            int j = rq * 8 + jj;
            float4 kv = *(const float4*)&cur[j * 260 + qd * 4];
            const float* ep = &s_e[(t * 32 + j) * 8];
            ulonglong2 e01 = *(const ulonglong2*)ep;
            ulonglong2 e23 = *(const ulonglong2*)(ep + 4);
            ull d0 = dup2(kv.x), d1 = dup2(kv.y), d2 = dup2(kv.z), d3 = dup2(kv.w);
            ffma2(ctxa[0][0], d0, e01.x); ffma2(ctxa[0][1], d1, e01.x);
            ffma2(ctxa[0][2], d2, e01.x); ffma2(ctxa[0][3], d3, e01.x);
            ffma2(ctxa[1][0], d0, e01.y); ffma2(ctxa[1][1], d1, e01.y);
            ffma2(ctxa[1][2], d2, e01.y); ffma2(ctxa[1][3], d3, e01.y);
            ffma2(ctxa[2][0], d0, e23.x); ffma2(ctxa[2][1], d1, e23.x);
            ffma2(ctxa[2][2], d2, e23.x); ffma2(ctxa[2][3], d3, e23.x);
            ffma2(ctxa[3][0], d0, e23.y); ffma2(ctxa[3][1], d1, e23.y);
            ffma2(ctxa[3][2], d2, e23.y); ffma2(ctxa[3][3], d3, e23.y);
        }
    }
    __syncthreads();

    // ---- per-head denominators (warp w = head w)
    {
        float sum = 0.0f;
        #pragma unroll
        for (int m = 0; m < 16; m++) sum += s_e[(lane + 32 * m) * 8 + wrp];
        #pragma unroll
        for (int off = 16; off >= 1; off >>= 1) sum += __shfl_xor_sync(0xFFFFFFFFu, sum, off);
        if (lane == 0) s_rdn[wrp] = 1.0f / sum;
    }
    __syncthreads();

    float rdn[NH];
    #pragma unroll
    for (int h = 0; h < NH; h++) rdn[h] = s_rdn[h];

    // ---- head_sum -> s_hs ; ctx partials -> s_red (aliases kv buffers)
    #pragma unroll
    for (int r = 0; r < 2; r++) {
        int j = tid + 256 * r;
        float4 w0 = ((const float4*)s_e)[j * 2];
        float4 w1 = ((const float4*)s_e)[j * 2 + 1];
        s_hs[j] = w0.x * rdn[0] + w0.y * rdn[1] + w0.z * rdn[2] + w0.w * rdn[3]
                + w1.x * rdn[4] + w1.y * rdn[5] + w1.z * rdn[6] + w1.w * rdn[7];
    }
    {
        float* s_red = sm + A_KV0;   // 4 x 2048 = 8192 floats, fits
        #pragma unroll
        for (int hp = 0; hp < 4; hp++)
            #pragma unroll
            for (int col = 0; col < 4; col++) {
                float lo, hi; unpack2(ctxa[hp][col], lo, hi);
                int d = qd * 4 + col;
                s_red[rq * 2048 + (2 * hp) * 256 + d]     = lo;
                s_red[rq * 2048 + (2 * hp + 1) * 256 + d] = hi;
            }
    }
    __syncthreads();

    // ---- final ctx: sum quarters, normalize, store [b][h*256+d]
    {
        const float* s_red = sm + A_KV0;
        #pragma unroll
        for (int k = 0; k < 8; k++) {
            int slot = tid + 256 * k;
            float v = s_red[slot] + s_red[2048 + slot] + s_red[4096 + slot] + s_red[6144 + slot];
            g_CTXF[(size_t)b * 2048 + slot] = v * rdn[slot >> 8];
        }
    }

    // ---- top-4 iterative argmax (lowest-index tie-break)
    const bool write_idx = (out_size >= IDX_BASE + IDX_ELEMS);
    for (int it = 0; it < TOPK; it++) {
        float v = s_hs[tid]; int idx = tid;
        float v1 = s_hs[tid + 256];
        if (v1 > v) { v = v1; idx = tid + 256; }
        #pragma unroll
        for (int off = 16; off >= 1; off >>= 1) {
            float ov = __shfl_xor_sync(0xFFFFFFFFu, v, off);
            int   oi = __shfl_xor_sync(0xFFFFFFFFu, idx, off);
            if (ov > v || (ov == v && oi < idx)) { v = ov; idx = oi; }
        }
        if (lane == 0) { s_wv[wrp] = v; s_wi[wrp] = idx; }
        __syncthreads();
        if (tid == 0) {
            float bv = s_wv[0]; int bi = s_wi[0];
            #pragma unroll
            for (int k = 1; k < 8; k++)
                if (s_wv[k] > bv || (s_wv[k] == bv && s_wi[k] < bi)) { bv = s_wv[k]; bi = s_wi[k]; }
            if (write_idx) outp[IDX_BASE + b * TOPK + it] = (float)bi;
            s_hs[bi] = -1e30f;
        }
        __syncthreads();
    }
}

// ========== out = sum of 8 split-K partials + bo ==========
__global__ __launch_bounds__(256) void k_out(const float* __restrict__ bo,
                                             float* __restrict__ outp) {
    int i = blockIdx.x * 256 + threadIdx.x;
    const float4* P4 = (const float4*)g_P;
    float4 acc = ((const float4*)bo)[i & 63];
    #pragma unroll
    for (int z = 0; z < 8; z++) {
        float4 p = P4[z * 32768 + i];
        acc.x += p.x; acc.y += p.y; acc.z += p.z; acc.w += p.w;
    }
    ((float4*)outp)[i] = acc;
}

// =============================== launch ===============================
extern "C" void kernel_launch(void* const* d_in, const int* in_sizes, int n_in,
                              void* d_out, int out_size) {
    const float* inp_q  = (const float*)d_in[0];
    const float* inp_kv = (const float*)d_in[1];
    const int*   amask  = (const int*)  d_in[2];
    const float* Wq     = (const float*)d_in[3];
    const float* Wk     = (const float*)d_in[4];
    const float* Wv     = (const float*)d_in[5];
    const float* Wo     = (const float*)d_in[6];
    const float* bo     = (const float*)d_in[7];
    float* outp = (float*)d_out;

    (void)cudaFuncSetAttribute(k_attn, cudaFuncAttributeMaxDynamicSharedMemorySize, AT_BYTES);

    k_mm64<<<dim3(8, 8, 1), 256>>>(inp_q, Wq, 0);    // g_Q = inp_q @ Wq
    k_mm64<<<dim3(4, 8, 8), 256>>>(nullptr, Wk, 1);  // g_T per-head fold
    k_mm64<<<dim3(4, 4, 8), 256>>>(Wv, Wo, 2);       // g_W2 = blockdiag(Wv) @ Wo
    k_attn<<<NB, 256, AT_BYTES>>>(inp_kv, amask, outp, out_size);
    k_mm64<<<dim3(4, 8, 8), 256>>>(nullptr, nullptr, 3);  // g_P = ctx @ W2 (split-K 8)
    k_out <<<128, 256>>>(bo, outp);
}

// round 9
// speedup vs baseline: 1.0807x; 1.0807x over previous
#include <cuda_runtime.h>
#include <cstdint>

#define NB    512
#define NKV   512
#define DIM   256
#define NH    8
#define DH    64
#define INNER 512
#define TOPK  4

#define OUT_ELEMS   (NB * DIM)
#define IDX_BASE    OUT_ELEMS
#define IDX_ELEMS   (NB * TOPK)

typedef unsigned long long ull;

// ---------------- device scratch ----------------
__device__ float g_Q   [NB * INNER];        // [b][h*64+e]
__device__ float g_T   [NB * 2048];         // [b][c*8+h]
__device__ float g_W2  [2048 * DIM];        // [(h*256+d)][o]
__device__ float g_CTXF[NB * 2048];         // [b][h*256+d]
__device__ float g_P   [8 * NB * DIM];      // split-K partials

// ---------------- helpers ----------------
__device__ __forceinline__ void ffma2(ull& d, ull a, ull b) {
    asm("fma.rn.f32x2 %0, %1, %2, %0;" : "+l"(d) : "l"(a), "l"(b));
}
__device__ __forceinline__ ull dup2(float x) {
    ull r; asm("mov.b64 %0, {%1, %1};" : "=l"(r) : "f"(x)); return r;
}
__device__ __forceinline__ void unpack2(ull v, float& lo, float& hi) {
    asm("mov.b64 {%0, %1}, %2;" : "=f"(lo), "=f"(hi) : "l"(v));
}
__device__ __forceinline__ uint32_t smem_u32(const void* p) {
    uint32_t a;
    asm("{ .reg .u64 t; cvta.to.shared.u64 t, %1; cvt.u32.u64 %0, t; }" : "=r"(a) : "l"(p));
    return a;
}
__device__ __forceinline__ void cpasync16(uint32_t dst, const void* src) {
    asm volatile("cp.async.cg.shared.global [%0], [%1], 16;" :: "r"(dst), "l"(src));
}
#define CP_COMMIT() asm volatile("cp.async.commit_group;")
#define CP_WAIT(n)  asm volatile("cp.async.wait_group %0;" :: "n"(n))

// ========== unified small GEMM: 64x64 tile, K in 64-chunks, f32x2 micro ==========
// mode 0: g_Q = inp_q(pA)[512x256] @ Wq(pB)[256x512]              grid(8,8,1)
// mode 1: g_T[b][c*8+h] = sum_e g_Q[b,h,e]*Wk(pB)[c,h,e]          grid(4,8,8) z=h
// mode 2: g_W2[(h*256+d)][o] = sum_e Wv(pA)[d,h,e]*Wo(pB)[h,e,o]  grid(4,4,8) z=h
// mode 3: g_P[z] = g_CTXF[:, z*256:+256] @ g_W2[z*256:+256,:]     grid(4,8,8) z=ksplit
__global__ __launch_bounds__(256) void k_mm64(const float* __restrict__ pA,
                                              const float* __restrict__ pB,
                                              int mode) {
    __shared__ float As[64 * 68];   // [k][m]
    __shared__ float Bs[64 * 68];   // [k][n]
    const int tid = threadIdx.x;
    const int tr = tid >> 4, tc = tid & 15;
    const int n0 = blockIdx.x * 64, m0 = blockIdx.y * 64;
    const int z = blockIdx.z;

    const float* A; const float* B; float* C;
    int lda, ldb, ldc, chunks; bool bkc = false, scat = false;
    if (mode == 0) {
        A = pA; lda = 256; B = pB; ldb = 512; C = g_Q; ldc = 512; chunks = 4;
    } else if (mode == 1) {
        A = g_Q + z * 64; lda = 512; B = pB + z * 64; ldb = 512;
        C = g_T; ldc = 2048; chunks = 1; bkc = true; scat = true;
    } else if (mode == 2) {
        A = pA + z * 64; lda = 512; B = pB + z * 64 * 256; ldb = 256;
        C = g_W2 + z * 65536; ldc = 256; chunks = 1;
    } else {
        A = g_CTXF + z * 256; lda = 2048; B = g_W2 + (size_t)z * 256 * 256; ldb = 256;
        C = g_P + (size_t)z * (NB * DIM); ldc = 256; chunks = 4;
    }

    ull acc[2][4];
    #pragma unroll
    for (int p = 0; p < 2; p++)
        #pragma unroll
        for (int j = 0; j < 4; j++) acc[p][j] = 0ull;

    for (int ch = 0; ch < chunks; ch++) {
        const int kb = ch * 64;
        #pragma unroll
        for (int s = 0; s < 16; s++) {
            int id = tid + 256 * s;
            int k = id & 63, m = id >> 6;
            As[k * 68 + m] = A[(size_t)(m0 + m) * lda + kb + k];
        }
        if (bkc) {
            #pragma unroll
            for (int s = 0; s < 16; s++) {
                int id = tid + 256 * s;
                int k = id & 63, n = id >> 6;
                Bs[k * 68 + n] = B[(size_t)(n0 + n) * ldb + kb + k];
            }
        } else {
            #pragma unroll
            for (int s = 0; s < 16; s++) {
                int id = tid + 256 * s;
                int n = id & 63, k = id >> 6;
                Bs[k * 68 + n] = B[(size_t)(kb + k) * ldb + n0 + n];
            }
        }
        __syncthreads();
        #pragma unroll 8
        for (int e = 0; e < 64; e++) {
            ulonglong2 a2 = *(const ulonglong2*)&As[e * 68 + tr * 4];
            float4 b4 = *(const float4*)&Bs[e * 68 + tc * 4];
            ull d0 = dup2(b4.x), d1 = dup2(b4.y), d2 = dup2(b4.z), d3 = dup2(b4.w);
            ffma2(acc[0][0], a2.x, d0); ffma2(acc[0][1], a2.x, d1);
            ffma2(acc[0][2], a2.x, d2); ffma2(acc[0][3], a2.x, d3);
            ffma2(acc[1][0], a2.y, d0); ffma2(acc[1][1], a2.y, d1);
            ffma2(acc[1][2], a2.y, d2); ffma2(acc[1][3], a2.y, d3);
        }
        __syncthreads();
    }

    #pragma unroll
    for (int p = 0; p < 2; p++) {
        #pragma unroll
        for (int j = 0; j < 4; j++) {
            float lo, hi; unpack2(acc[p][j], lo, hi);
            int m = m0 + tr * 4 + 2 * p;
            int n = n0 + tc * 4 + j;
            if (scat) {
                g_T[(size_t)m * 2048 + n * 8 + z]       = lo;
                g_T[(size_t)(m + 1) * 2048 + n * 8 + z] = hi;
            } else {
                C[(size_t)m * ldc + n]       = lo;
                C[(size_t)(m + 1) * ldc + n] = hi;
            }
        }
    }
}

// ========== attention: 32 x 16-row kv tiles, cp.async double-buffered ==========
#define A_KV0 0                    // 16*260 = 4160 floats
#define A_KV1 4160
#define A_T   8320                 // 2048  [c][h]
#define A_E   10368                // 4096  [j][h]
#define A_PF  14464                // 3072  [cg16][j16 stride 6 ull][hp]
#define A_NEG 17536                // 512
#define A_HS  18048                // 512
#define A_RDN 18560                // 8
#define A_WV  18568                // 8
#define A_WI  18576                // 8
#define A_FLOATS 18584
#define AT_BYTES (A_FLOATS * 4)    // 74336 B; 3 CTAs = 223008 <= 227KB

__global__ __launch_bounds__(256, 3) void k_attn(
        const float* __restrict__ kv_all, const int* __restrict__ mask_all,
        float* __restrict__ outp, int out_size) {
    extern __shared__ float sm[];
    float* s_t   = sm + A_T;
    float* s_e   = sm + A_E;
    float* s_neg = sm + A_NEG;
    float* s_hs  = sm + A_HS;
    float* s_rdn = sm + A_RDN;
    float* s_wv  = sm + A_WV;
    int*   s_wi  = (int*)(sm + A_WI);
    ull*   pf    = (ull*)(sm + A_PF);

    const int b   = blockIdx.x;
    const int tid = threadIdx.x;
    const int wrp = tid >> 5, lane = tid & 31;
    const int rp  = tid & 15, cg = tid >> 4;     // pass1: row rp, cols [cg*16, cg*16+16)
    const int qd  = tid & 63, rq = tid >> 6;     // ctx: cols 4qd..+3, rows rq*4..+3

    const float4* kvg = (const float4*)(kv_all + (size_t)b * NKV * DIM);

    // per-thread cp.async addressing: 4 x 16B chunks of a 16x256 tile
    uint32_t kvbase[2] = { smem_u32(sm + A_KV0), smem_u32(sm + A_KV1) };
    uint32_t doff[4];
    #pragma unroll
    for (int s = 0; s < 4; s++) {
        int id = tid + 256 * s;
        doff[s] = (uint32_t)((id >> 6) * 260 + (id & 63) * 4) * 4u;
    }

    // issue tile 0
    #pragma unroll
    for (int s = 0; s < 4; s++) {
        int id = tid + 256 * s;
        cpasync16(kvbase[0] + doff[s], kvg + (id >> 6) * 64 + (id & 63));
    }
    CP_COMMIT();

    // T[b] -> s_t ; mask -> s_neg
    {
        const float4* T4 = (const float4*)(g_T + (size_t)b * 2048);
        ((float4*)s_t)[tid]       = T4[tid];
        ((float4*)s_t)[tid + 256] = T4[tid + 256];
        const int* mb = mask_all + b * NKV;
        s_neg[tid]       = mb[tid]       ? 0.0f : -10000.0f;
        s_neg[tid + 256] = mb[tid + 256] ? 0.0f : -10000.0f;
    }

    ull ctxa[4][4];
    #pragma unroll
    for (int i = 0; i < 4; i++)
        #pragma unroll
        for (int j = 0; j < 4; j++) ctxa[i][j] = 0ull;

    for (int t = 0; t < 32; t++) {
        __syncthreads();   // all warps done with the idle buffer (ctx of t-1) and prev e/pf

        // issue tile t+1 into the idle buffer FIRST...
        if (t < 31) {
            uint32_t nb = kvbase[(t + 1) & 1];
            const float4* gs = kvg + (t + 1) * 16 * 64;
            #pragma unroll
            for (int s = 0; s < 4; s++) {
                int id = tid + 256 * s;
                cpasync16(nb + doff[s], gs + (id >> 6) * 64 + (id & 63));
            }
            CP_COMMIT();
            CP_WAIT(1);    // ...then retire tile t (t and t+1 pending -> wait leaves only t+1)
        } else {
            CP_WAIT(0);    // last tile: drain everything
        }
        __syncthreads();   // cross-thread visibility of tile t

        const float* cur = sm + ((t & 1) ? A_KV1 : A_KV0);

        // ---- pass1: row rp, 16 cols of group cg, all 8 heads
        ull acc[4] = {0ull, 0ull, 0ull, 0ull};
        const int c0 = cg * 16;
        #pragma unroll
        for (int c4 = 0; c4 < 16; c4 += 4) {
            float4 ka = *(const float4*)&cur[rp * 260 + c0 + c4];
            float kf[4] = {ka.x, ka.y, ka.z, ka.w};
            #pragma unroll
            for (int cc = 0; cc < 4; cc++) {
                const float* tp = &s_t[(c0 + c4 + cc) * 8];
                ulonglong2 t01 = *(const ulonglong2*)tp;
                ulonglong2 t23 = *(const ulonglong2*)(tp + 4);
                ull da = dup2(kf[cc]);
                ffma2(acc[0], da, t01.x); ffma2(acc[1], da, t01.y);
                ffma2(acc[2], da, t23.x); ffma2(acc[3], da, t23.y);
            }
        }
        {   // pf ull layout: cg*96 + rp*6 + hp (even base -> 16B-aligned stores)
            ulonglong2* sp2 = (ulonglong2*)(pf + cg * 96 + rp * 6);
            sp2[0] = make_ulonglong2(acc[0], acc[1]);
            sp2[1] = make_ulonglong2(acc[2], acc[3]);
        }
        __syncthreads();

        // ---- reduce 16 c-groups + exp (threads 0..127 own (j,h))
        if (tid < 128) {
            int j = tid >> 3, h = tid & 7;
            const float* pfF = (const float*)pf;
            float sum = 0.0f;
            #pragma unroll
            for (int g = 0; g < 16; g++) sum += pfF[g * 192 + j * 12 + h];
            s_e[(t * 16 + j) * 8 + h] = __expf(sum * 0.125f + s_neg[t * 16 + j]);
        }
        __syncthreads();

        // ---- ctx accumulate (4 rows per thread)
        #pragma unroll
        for (int jj = 0; jj < 4; jj++) {
            int j = rq * 4 + jj;
            float4 kv = *(const float4*)&cur[j * 260 + qd * 4];
            const float* ep = &s_e[(t * 16 + j) * 8];
            ulonglong2 e01 = *(const ulonglong2*)ep;
            ulonglong2 e23 = *(const ulonglong2*)(ep + 4);
            ull d0 = dup2(kv.x), d1 = dup2(kv.y), d2 = dup2(kv.z), d3 = dup2(kv.w);
            ffma2(ctxa[0][0], d0, e01.x); ffma2(ctxa[0][1], d1, e01.x);
            ffma2(ctxa[0][2], d2, e01.x); ffma2(ctxa[0][3], d3, e01.x);
            ffma2(ctxa[1][0], d0, e01.y); ffma2(ctxa[1][1], d1, e01.y);
            ffma2(ctxa[1][2], d2, e01.y); ffma2(ctxa[1][3], d3, e01.y);
            ffma2(ctxa[2][0], d0, e23.x); ffma2(ctxa[2][1], d1, e23.x);
            ffma2(ctxa[2][2], d2, e23.x); ffma2(ctxa[2][3], d3, e23.x);
            ffma2(ctxa[3][0], d0, e23.y); ffma2(ctxa[3][1], d1, e23.y);
            ffma2(ctxa[3][2], d2, e23.y); ffma2(ctxa[3][3], d3, e23.y);
        }
    }
    __syncthreads();

    // ---- per-head denominators (warp w = head w)
    {
        float sum = 0.0f;
        #pragma unroll
        for (int m = 0; m < 16; m++) sum += s_e[(lane + 32 * m) * 8 + wrp];
        #pragma unroll
        for (int off = 16; off >= 1; off >>= 1) sum += __shfl_xor_sync(0xFFFFFFFFu, sum, off);
        if (lane == 0) s_rdn[wrp] = 1.0f / sum;
    }
    __syncthreads();

    float rdn[NH];
    #pragma unroll
    for (int h = 0; h < NH; h++) rdn[h] = s_rdn[h];

    // ---- head_sum -> s_hs ; ctx partials -> s_red (aliases kv region: 8192 <= 8320)
    #pragma unroll
    for (int r = 0; r < 2; r++) {
        int j = tid + 256 * r;
        float4 w0 = ((const float4*)s_e)[j * 2];
        float4 w1 = ((const float4*)s_e)[j * 2 + 1];
        s_hs[j] = w0.x * rdn[0] + w0.y * rdn[1] + w0.z * rdn[2] + w0.w * rdn[3]
                + w1.x * rdn[4] + w1.y * rdn[5] + w1.z * rdn[6] + w1.w * rdn[7];
    }
    {
        float* s_red = sm + A_KV0;
        #pragma unroll
        for (int hp = 0; hp < 4; hp++)
            #pragma unroll
            for (int col = 0; col < 4; col++) {
                float lo, hi; unpack2(ctxa[hp][col], lo, hi);
                int d = qd * 4 + col;
                s_red[rq * 2048 + (2 * hp) * 256 + d]     = lo;
                s_red[rq * 2048 + (2 * hp + 1) * 256 + d] = hi;
            }
    }
    __syncthreads();

    // ---- final ctx: sum quarters, normalize, store [b][h*256+d]
    {
        const float* s_red = sm + A_KV0;
        #pragma unroll
        for (int k = 0; k < 8; k++) {
            int slot = tid + 256 * k;
            float v = s_red[slot] + s_red[2048 + slot] + s_red[4096 + slot] + s_red[6144 + slot];
            g_CTXF[(size_t)b * 2048 + slot] = v * rdn[slot >> 8];
        }
    }

    // ---- top-4 iterative argmax (lowest-index tie-break, matches lax.top_k)
    const bool write_idx = (out_size >= IDX_BASE + IDX_ELEMS);
    for (int it = 0; it < TOPK; it++) {
        float v = s_hs[tid]; int idx = tid;
        float v1 = s_hs[tid + 256];
        if (v1 > v) { v = v1; idx = tid + 256; }
        #pragma unroll
        for (int off = 16; off >= 1; off >>= 1) {
            float ov = __shfl_xor_sync(0xFFFFFFFFu, v, off);
            int   oi = __shfl_xor_sync(0xFFFFFFFFu, idx, off);
            if (ov > v || (ov == v && oi < idx)) { v = ov; idx = oi; }
        }
        if (lane == 0) { s_wv[wrp] = v; s_wi[wrp] = idx; }
        __syncthreads();
        if (tid == 0) {
            float bv = s_wv[0]; int bi = s_wi[0];
            #pragma unroll
            for (int k = 1; k < 8; k++)
                if (s_wv[k] > bv || (s_wv[k] == bv && s_wi[k] < bi)) { bv = s_wv[k]; bi = s_wi[k]; }
            if (write_idx) outp[IDX_BASE + b * TOPK + it] = (float)bi;
            s_hs[bi] = -1e30f;
        }
        __syncthreads();
    }
}

// ========== out = sum of 8 split-K partials + bo ==========
__global__ __launch_bounds__(256) void k_out(const float* __restrict__ bo,
                                             float* __restrict__ outp) {
    int i = blockIdx.x * 256 + threadIdx.x;
    const float4* P4 = (const float4*)g_P;
    float4 acc = ((const float4*)bo)[i & 63];
    #pragma unroll
    for (int z = 0; z < 8; z++) {
        float4 p = P4[z * 32768 + i];
        acc.x += p.x; acc.y += p.y; acc.z += p.z; acc.w += p.w;
    }
    ((float4*)outp)[i] = acc;
}

// =============================== launch ===============================
extern "C" void kernel_launch(void* const* d_in, const int* in_sizes, int n_in,
                              void* d_out, int out_size) {
    const float* inp_q  = (const float*)d_in[0];
    const float* inp_kv = (const float*)d_in[1];
    const int*   amask  = (const int*)  d_in[2];
    const float* Wq     = (const float*)d_in[3];
    const float* Wk     = (const float*)d_in[4];
    const float* Wv     = (const float*)d_in[5];
    const float* Wo     = (const float*)d_in[6];
    const float* bo     = (const float*)d_in[7];
    float* outp = (float*)d_out;

    (void)cudaFuncSetAttribute(k_attn, cudaFuncAttributeMaxDynamicSharedMemorySize, AT_BYTES);

    k_mm64<<<dim3(8, 8, 1), 256>>>(inp_q, Wq, 0);      // g_Q = inp_q @ Wq
    k_mm64<<<dim3(4, 8, 8), 256>>>(nullptr, Wk, 1);    // g_T fold (per head)
    k_mm64<<<dim3(4, 4, 8), 256>>>(Wv, Wo, 2);         // g_W2 = blockdiag(Wv) @ Wo
    k_attn<<<NB, 256, AT_BYTES>>>(inp_kv, amask, outp, out_size);
    k_mm64<<<dim3(4, 8, 8), 256>>>(nullptr, nullptr, 3);  // g_P = ctx @ W2 (split-K 8)
    k_out <<<128, 256>>>(bo, outp);
}